// round 6
// baseline (speedup 1.0000x reference)
#include <cuda_runtime.h>

// Problem constants (fixed by the reference: B=8, H=W=512, C=32, n_segments=256)
#define B_    8
#define HW_   (512 * 512)            // 262144 pixels per batch
#define C_    32
#define S_    256
#define CHUNKS_PER_BATCH 64
#define NCTA  (B_ * CHUNKS_PER_BATCH)   // 512 CTAs, one contiguous chunk each
#define CHUNK (HW_ / CHUNKS_PER_BATCH)  // 4096 pixels
#define WARPS 8
#define SEGW  (S_ / WARPS)              // 32 segments owned per warp

// Partial results scratch (overwritten fully every launch -> no zeroing needed,
// no cross-replay state, fully deterministic: zero atomics in this kernel).
__device__ float          g_psum[(size_t)NCTA * S_ * C_];   // 16 MB
__device__ unsigned short g_pcnt[(size_t)NCTA * S_ * C_];   //  8 MB

// ---------------------------------------------------------------------------
// Kernel 1: sequential stream over the image. Warp-private smem accumulators,
// segment ownership partitioned by warp -> no atomics, no races.
// smem: fp32 sums [8][32][32] (32 KB) + u16 counts [8][32][32] (16 KB) = 48 KB.
// 4 CTAs/SM -> all 512 CTAs resident in a single wave.
// ---------------------------------------------------------------------------
__global__ void __launch_bounds__(256) k_accum(const float* __restrict__ img,
                                               const int* __restrict__ slic) {
    extern __shared__ char smem[];
    float*          s_sum = (float*)smem;                         // 8*32*32 f32
    unsigned short* s_cnt = (unsigned short*)(smem + WARPS * SEGW * C_ * 4);

    const int tid  = threadIdx.x;
    const int w    = tid >> 5;
    const int lane = tid & 31;
    const int lo   = w * SEGW;

    for (int i = tid; i < WARPS * SEGW * C_; i += 256) { s_sum[i] = 0.f; s_cnt[i] = 0; }
    __syncthreads();

    const size_t pix0 = (size_t)blockIdx.x * CHUNK;   // linear pixel base (covers batch too)
    float*          wsum = s_sum + w * SEGW * C_;
    unsigned short* wcnt = s_cnt + w * SEGW * C_;

    for (int base = 0; base < CHUNK; base += 32) {
        // Coalesced id load; the 8 warps share these lines via L1.
        int id = slic[pix0 + base + lane] - 1;              // 1-based; 0 -> -1 dropped
        bool mine = ((unsigned)(id - lo)) < (unsigned)SEGW;
        unsigned mask = __ballot_sync(0xffffffffu, mine);

        while (mask) {
            // Batch up to 8 owned pixels: issue all 8 independent 128B row
            // loads before consuming -> MLP ~8 per warp.
            int js[8]; float vs[8]; int n = 0;
            #pragma unroll
            for (int t = 0; t < 8; t++) {
                js[t] = 0;
                if (mask) { js[t] = __ffs(mask) - 1; mask &= mask - 1; n = t + 1; }
            }
            #pragma unroll
            for (int t = 0; t < 8; t++)
                if (t < n)
                    vs[t] = __ldg(img + (pix0 + base + js[t]) * C_ + lane); // full 128B line
            #pragma unroll
            for (int t = 0; t < 8; t++)
                if (t < n) {
                    int segl = __shfl_sync(0xffffffffu, id, js[t]) - lo;    // js uniform
                    float v = vs[t];
                    wsum[segl * C_ + lane] += v;                // conflict-free (lane=bank)
                    wcnt[segl * C_ + lane] += (v != 0.0f);      // per-channel nonzero count
                }
        }
    }

    // Write this chunk's partials (warp-private -> no sync needed before read).
    const size_t ob = (size_t)blockIdx.x * S_ * C_;
    #pragma unroll 4
    for (int segl = 0; segl < SEGW; segl++) {
        g_psum[ob + (lo + segl) * C_ + lane] = wsum[segl * C_ + lane];
        g_pcnt[ob + (lo + segl) * C_ + lane] = wcnt[segl * C_ + lane];
    }
}

// ---------------------------------------------------------------------------
// Kernel 2: reduce 64 chunk-partials per (batch, segment) and divide.
// grid = 2048 warps, lane = channel. 24 MB scratch read, fixed order ->
// deterministic. 0/0 -> NaN matches the reference for empty segments.
// ---------------------------------------------------------------------------
__global__ void __launch_bounds__(32) k_final(float* __restrict__ out) {
    int bs = blockIdx.x;            // b*256 + s
    int b = bs >> 8, s = bs & (S_ - 1);
    int lane = threadIdx.x;

    float sum = 0.0f;
    int   cnt = 0;
    #pragma unroll 8
    for (int k = 0; k < CHUNKS_PER_BATCH; k++) {
        size_t idx = ((size_t)(b * CHUNKS_PER_BATCH + k) * S_ + s) * C_ + lane;
        sum += g_psum[idx];
        cnt += (int)g_pcnt[idx];
    }
    out[((size_t)s * B_ + b) * C_ + lane] = sum / (float)cnt;
}

// ---------------------------------------------------------------------------
// d_in[0] = image_output [8,512,512,32] f32 (contiguous -> linear pixel rows)
// d_in[1] = slic_output  [8,512,512,1]  i32
// d_in[2] = n_segments (fixed 256, compiled in)
// d_out   = [256, 8, 32] f32
// ---------------------------------------------------------------------------
extern "C" void kernel_launch(void* const* d_in, const int* in_sizes, int n_in,
                              void* d_out, int out_size) {
    const float* img  = (const float*)d_in[0];
    const int*   slic = (const int*)d_in[1];
    float*       out  = (float*)d_out;

    const int smem_bytes = WARPS * SEGW * C_ * (4 + 2);   // 49152
    cudaFuncSetAttribute(k_accum, cudaFuncAttributeMaxDynamicSharedMemorySize, smem_bytes);

    k_accum<<<NCTA, 256, smem_bytes>>>(img, slic);
    k_final<<<B_ * S_, 32>>>(out);
}

// round 7
// speedup vs baseline: 1.3886x; 1.3886x over previous
#include <cuda_runtime.h>

// Fixed problem shape: B=8, H=W=512, C=32, n_segments=256
#define B_    8
#define HW_   (512 * 512)        // 262144 px per batch
#define C_    32
#define S_    256
#define NCTA  256                // CTAs; 32 per batch
#define CPB   (NCTA / B_)        // 32 chunks per batch
#define CHUNK (HW_ / CPB)        // 8192 px per CTA (contiguous, never straddles batch)
#define BP    128                // pixels per staged block (16 KB image data)
#define NB    (CHUNK / BP)       // 64 blocks per CTA
#define WARPS 8
#define SEGW  (S_ / WARPS)       // 32 segments owned per warp

// Per-CTA partials. Fully overwritten each launch -> no zeroing, replay-safe.
__device__ float          g_psum[(size_t)NCTA * S_ * C_];   // 8 MB
__device__ unsigned short g_pcnt[(size_t)NCTA * S_ * C_];   // 4 MB

__device__ __forceinline__ unsigned smem_u32(const void* p) {
    return (unsigned)__cvta_generic_to_shared(p);
}
__device__ __forceinline__ void cp16(unsigned dst, const void* src) {
    asm volatile("cp.async.cg.shared.global [%0], [%1], 16;" :: "r"(dst), "l"(src));
}

// ---------------------------------------------------------------------------
// k_accum: double-buffered cp.async streaming copy (DRAM-saturating, async)
// overlapped with smem-resident segment accumulation (warp-private bins,
// zero atomics). smem: bins 48KB + 2x(16KB img + 512B ids) = 81 KB -> 2 CTA/SM.
// ---------------------------------------------------------------------------
__global__ void __launch_bounds__(256) k_accum(const float* __restrict__ img,
                                               const int* __restrict__ slic) {
    extern __shared__ char smem[];
    float*          s_sum = (float*)smem;                          // [256][32] f32, 32 KB
    unsigned short* s_cnt = (unsigned short*)(smem + 32768);       // [256][32] u16, 16 KB
    float*          s_buf = (float*)(smem + 49152);                // [2][128][32] f32, 32 KB
    int*            s_ids = (int*)(smem + 49152 + 32768);          // [2][128] i32, 1 KB

    const int tid = threadIdx.x, w = tid >> 5, lane = tid & 31, lo = w * SEGW;

    for (int i = tid; i < S_ * C_; i += 256) { s_sum[i] = 0.f; s_cnt[i] = 0; }

    const size_t pix0 = (size_t)blockIdx.x * CHUNK;

    // Prefetch block 0 into buffer 0.
    {
        const char* src = (const char*)(img + pix0 * C_);
        unsigned d = smem_u32(s_buf);
        #pragma unroll
        for (int k = 0; k < 4; k++)
            cp16(d + (unsigned)(tid + k * 256) * 16, src + (size_t)(tid + k * 256) * 16);
        if (tid < 32)
            cp16(smem_u32(s_ids) + tid * 16, (const char*)(slic + pix0) + tid * 16);
        asm volatile("cp.async.commit_group;");
    }

    float*          wsum = s_sum + lo * C_;
    unsigned short* wcnt = s_cnt + lo * C_;

    for (int g = 0; g < NB; g++) {
        const int cur = g & 1;
        if (g + 1 < NB) {
            const int nxt = cur ^ 1;
            const char* src = (const char*)(img + (pix0 + (size_t)(g + 1) * BP) * C_);
            unsigned d = smem_u32(s_buf + nxt * BP * C_);
            #pragma unroll
            for (int k = 0; k < 4; k++)
                cp16(d + (unsigned)(tid + k * 256) * 16, src + (size_t)(tid + k * 256) * 16);
            if (tid < 32)
                cp16(smem_u32(s_ids + nxt * BP) + tid * 16,
                     (const char*)(slic + pix0 + (size_t)(g + 1) * BP) + tid * 16);
            asm volatile("cp.async.commit_group;");
            asm volatile("cp.async.wait_group 1;");   // groups retire in order -> buf[cur] ready
        } else {
            asm volatile("cp.async.wait_group 0;");
        }
        __syncthreads();

        const float* buf = s_buf + cur * BP * C_;
        const int*   ids = s_ids + cur * BP;

        #pragma unroll
        for (int t = 0; t < BP / 32; t++) {
            int id = ids[t * 32 + lane] - 1;                       // 1-based; 0 -> -1 dropped
            unsigned m = __ballot_sync(0xffffffffu,
                                       ((unsigned)(id - lo)) < (unsigned)SEGW);
            while (m) {
                int j0 = __ffs(m) - 1; m &= m - 1;
                int j1 = m ? (__ffs(m) - 1) : -1; if (j1 >= 0) m &= m - 1;
                int s0 = __shfl_sync(0xffffffffu, id, j0) - lo;
                int s1 = __shfl_sync(0xffffffffu, id, j1 >= 0 ? j1 : j0) - lo;
                float v0 = buf[(t * 32 + j0) * C_ + lane];
                float v1 = (j1 >= 0) ? buf[(t * 32 + j1) * C_ + lane] : 0.f;
                wsum[s0 * C_ + lane] += v0;                        // conflict-free: lane=bank
                wcnt[s0 * C_ + lane] += (unsigned short)(v0 != 0.f);
                if (j1 >= 0) {                                     // in-order smem pipe keeps
                    wsum[s1 * C_ + lane] += v1;                    // s0==s1 case correct
                    wcnt[s1 * C_ + lane] += (unsigned short)(v1 != 0.f);
                }
            }
        }
        __syncthreads();   // buf[cur] free for the g+2 prefetch
    }

    // Write this chunk's partials (own warp's bins -> no extra sync needed).
    const size_t ob = (size_t)blockIdx.x * S_ * C_;
    #pragma unroll 4
    for (int sgl = 0; sgl < SEGW; sgl++) {
        g_psum[ob + (lo + sgl) * C_ + lane] = wsum[sgl * C_ + lane];
        g_pcnt[ob + (lo + sgl) * C_ + lane] = wcnt[sgl * C_ + lane];
    }
}

// ---------------------------------------------------------------------------
// k_final: reduce 32 chunk-partials per (batch, segment), divide. Fixed order
// -> deterministic. 0/0 -> NaN matches reference for empty segments.
// ---------------------------------------------------------------------------
__global__ void __launch_bounds__(32) k_final(float* __restrict__ out) {
    int bs = blockIdx.x, b = bs >> 8, s = bs & (S_ - 1), lane = threadIdx.x;
    float sum = 0.f; int cnt = 0;
    #pragma unroll 8
    for (int k = 0; k < CPB; k++) {
        size_t idx = ((size_t)(b * CPB + k) * S_ + s) * C_ + lane;
        sum += g_psum[idx];
        cnt += (int)g_pcnt[idx];
    }
    out[((size_t)s * B_ + b) * C_ + lane] = sum / (float)cnt;
}

// ---------------------------------------------------------------------------
// d_in[0] = image_output [8,512,512,32] f32
// d_in[1] = slic_output  [8,512,512,1]  i32
// d_in[2] = n_segments (fixed 256, compiled in)
// d_out   = [256, 8, 32] f32
// ---------------------------------------------------------------------------
extern "C" void kernel_launch(void* const* d_in, const int* in_sizes, int n_in,
                              void* d_out, int out_size) {
    const float* img  = (const float*)d_in[0];
    const int*   slic = (const int*)d_in[1];
    float*       out  = (float*)d_out;

    const int smem_bytes = 32768 + 16384 + 32768 + 1024;   // 82944
    cudaFuncSetAttribute(k_accum, cudaFuncAttributeMaxDynamicSharedMemorySize, smem_bytes);

    k_accum<<<NCTA, 256, smem_bytes>>>(img, slic);
    k_final<<<B_ * S_, 32>>>(out);
}

// round 8
// speedup vs baseline: 1.9355x; 1.3939x over previous
#include <cuda_runtime.h>

// Fixed problem shape: B=8, H=W=512, C=32, n_segments=256
#define B_    8
#define HW_   (512 * 512)
#define C_    32
#define S_    256
#define CPB_  37                  // CTAs per batch
#define NCTA  (B_ * CPB_)         // 296 = 2 x 148 SMs -> one balanced wave
#define TPB   512
#define WARPS 16
#define SEGW  (S_ / WARPS)        // 16 segments owned per warp
#define BP    128                 // pixels per staged block (16 KB image data)
#define UPB   (HW_ / BP)          // 2048 copy units per batch

// Per-CTA partials (float2: .x = sum, .y = count). Fully overwritten each
// launch -> no zeroing, replay-safe, zero atomics -> deterministic.
__device__ float2 g_part[(size_t)NCTA * S_ * C_];   // ~19.4 MB

__device__ __forceinline__ unsigned smem_u32(const void* p) {
    return (unsigned)__cvta_generic_to_shared(p);
}
__device__ __forceinline__ void cp16(unsigned dst, const void* src) {
    asm volatile("cp.async.cg.shared.global [%0], [%1], 16;" :: "r"(dst), "l"(src));
}

// ---------------------------------------------------------------------------
// k_accum: 512 threads (16 warps -> 8/SMSP at 2 CTA/SM) streaming the image
// sequentially via double-buffered cp.async, accumulating into warp-private
// float2 smem bins (sum+count fused -> 3 smem ops per pixel, no atomics).
// smem: bins 64KB + 2 x (16KB img + 512B ids) = ~99 KB -> 2 CTAs/SM.
// Each CTA's unit range lies entirely within one batch (CPB_ CTAs per batch).
// ---------------------------------------------------------------------------
__global__ void __launch_bounds__(TPB, 2) k_accum(const float* __restrict__ img,
                                                  const int* __restrict__ slic) {
    extern __shared__ char smem[];
    float2* s_bin = (float2*)smem;                            // [256][32] f32x2, 64 KB
    float*  s_buf = (float*)(smem + 65536);                   // [2][128][32] f32, 32 KB
    int*    s_ids = (int*)(smem + 65536 + 32768);             // [2][128] i32, 1 KB

    const int tid = threadIdx.x, w = tid >> 5, lane = tid & 31;
    const int lo = w * SEGW;

    #pragma unroll
    for (int i = tid; i < S_ * C_; i += TPB) s_bin[i] = make_float2(0.f, 0.f);

    // Per-batch contiguous unit range (55 or 56 units), never straddles batch.
    const int batch = blockIdx.x / CPB_;
    const int c     = blockIdx.x % CPB_;
    const int u0 = batch * UPB + (c * UPB) / CPB_;
    const int u1 = batch * UPB + ((c + 1) * UPB) / CPB_;
    const int nb = u1 - u0;

    // Prefetch unit u0 into stage 0.
    {
        const char* src = (const char*)(img + (size_t)u0 * BP * C_);
        unsigned d = smem_u32(s_buf);
        cp16(d + (unsigned)tid * 16,         src + (size_t)tid * 16);
        cp16(d + (unsigned)(tid + TPB) * 16, src + (size_t)(tid + TPB) * 16);
        if (tid < 32)
            cp16(smem_u32(s_ids) + tid * 16, (const char*)(slic + (size_t)u0 * BP) + tid * 16);
        asm volatile("cp.async.commit_group;");
    }

    float2* wbin = s_bin + lo * C_;

    for (int g = 0; g < nb; g++) {
        const int cur = g & 1;
        if (g + 1 < nb) {
            const int nxt = cur ^ 1;
            const size_t u = (size_t)(u0 + g + 1) * BP;
            const char* src = (const char*)(img + u * C_);
            unsigned d = smem_u32(s_buf + nxt * BP * C_);
            cp16(d + (unsigned)tid * 16,         src + (size_t)tid * 16);
            cp16(d + (unsigned)(tid + TPB) * 16, src + (size_t)(tid + TPB) * 16);
            if (tid < 32)
                cp16(smem_u32(s_ids + nxt * BP) + tid * 16,
                     (const char*)(slic + u) + tid * 16);
            asm volatile("cp.async.commit_group;");
            asm volatile("cp.async.wait_group 1;");   // in-order retire -> stage cur ready
        } else {
            asm volatile("cp.async.wait_group 0;");
        }
        __syncthreads();

        const float* buf = s_buf + cur * BP * C_;
        const int*   ids = s_ids + cur * BP;

        #pragma unroll
        for (int t = 0; t < BP / 32; t++) {
            int id = ids[t * 32 + lane] - 1;               // 1-based; 0 -> -1 dropped
            unsigned m = __ballot_sync(0xffffffffu,
                                       ((unsigned)(id - lo)) < (unsigned)SEGW);
            while (m) {
                int j0 = __ffs(m) - 1; m &= m - 1;
                int j1 = m ? (__ffs(m) - 1) : -1; if (j1 >= 0) m &= m - 1;
                int s0 = __shfl_sync(0xffffffffu, id, j0) - lo;
                int s1 = __shfl_sync(0xffffffffu, id, j1 >= 0 ? j1 : j0) - lo;
                float v0 = buf[(t * 32 + j0) * C_ + lane];
                float v1 = (j1 >= 0) ? buf[(t * 32 + j1) * C_ + lane] : 0.f;
                float2 b0 = wbin[s0 * C_ + lane];          // LDS.64
                b0.x += v0; b0.y += (v0 != 0.f) ? 1.f : 0.f;
                wbin[s0 * C_ + lane] = b0;                 // STS.64
                if (j1 >= 0) {                             // same-thread smem ops are
                    float2 b1 = wbin[s1 * C_ + lane];      // in-order -> s0==s1 correct
                    b1.x += v1; b1.y += (v1 != 0.f) ? 1.f : 0.f;
                    wbin[s1 * C_ + lane] = b1;
                }
            }
        }
        __syncthreads();   // stage cur free for the g+2 prefetch
    }

    // Write this CTA's partials (own warp's bins -> no extra sync needed).
    const size_t ob = (size_t)blockIdx.x * S_ * C_;
    #pragma unroll
    for (int sgl = 0; sgl < SEGW; sgl++)
        g_part[ob + (lo + sgl) * C_ + lane] = wbin[sgl * C_ + lane];
}

// ---------------------------------------------------------------------------
// k_final: reduce the 37 per-batch CTA partials for each (b, s), divide.
// 4 warps split the chunk list, smem combine. Fixed order -> deterministic.
// 0/0 -> NaN matches the reference for empty segments.
// ---------------------------------------------------------------------------
__global__ void __launch_bounds__(128) k_final(float* __restrict__ out) {
    __shared__ float2 red[4][32];
    int bs = blockIdx.x, b = bs >> 8, s = bs & (S_ - 1);
    int lane = threadIdx.x & 31, w = threadIdx.x >> 5;

    float2 acc = make_float2(0.f, 0.f);
    for (int k = w; k < CPB_; k += 4) {
        size_t idx = ((size_t)(b * CPB_ + k) * S_ + s) * C_ + lane;
        float2 p = g_part[idx];
        acc.x += p.x; acc.y += p.y;
    }
    red[w][lane] = acc;
    __syncthreads();
    if (w == 0) {
        float sum = red[0][lane].x + red[1][lane].x + red[2][lane].x + red[3][lane].x;
        float cnt = red[0][lane].y + red[1][lane].y + red[2][lane].y + red[3][lane].y;
        out[((size_t)s * B_ + b) * C_ + lane] = sum / cnt;
    }
}

// ---------------------------------------------------------------------------
// d_in[0] = image_output [8,512,512,32] f32
// d_in[1] = slic_output  [8,512,512,1]  i32
// d_in[2] = n_segments (fixed 256, compiled in)
// d_out   = [256, 8, 32] f32
// ---------------------------------------------------------------------------
extern "C" void kernel_launch(void* const* d_in, const int* in_sizes, int n_in,
                              void* d_out, int out_size) {
    const float* img  = (const float*)d_in[0];
    const int*   slic = (const int*)d_in[1];
    float*       out  = (float*)d_out;

    const int smem_bytes = 65536 + 32768 + 1024;   // 99328 -> 2 CTAs/SM
    cudaFuncSetAttribute(k_accum, cudaFuncAttributeMaxDynamicSharedMemorySize, smem_bytes);

    k_accum<<<NCTA, TPB, smem_bytes>>>(img, slic);
    k_final<<<B_ * S_, 128>>>(out);
}